// round 1
// baseline (speedup 1.0000x reference)
#include <cuda_runtime.h>
#include <cstddef>

// ---------------- problem constants ----------------
#define L_LAYERS 3
#define H_HEADS  4
#define NN       26       // nodes
#define FF       26       // features
#define FP       28       // padded feature dim (multiple of 4)
#define BB       8        // batch elements per GAT block
#define GAT_THREADS (BB*NN)   // 208
#define KDIM     (NN*FF)  // 676
#define HID      256

// MLP GEMM tiling
#define MBM 64
#define MBN 256
#define MBK 26            // 676 = 26 * 26 exact

// scratch for flattened GAT output: [B, 676]  (static device alloc = allowed)
__device__ float g_flat[16384 * KDIM];

// =====================================================================
// GAT kernel: 3 layers fused. Block = 8 batch elems x 26 nodes.
// =====================================================================
__global__ __launch_bounds__(GAT_THREADS)
void gat_kernel(const float* __restrict__ x,
                const float* __restrict__ W,
                const float* __restrict__ a_src,
                const float* __restrict__ a_dst,
                int batch)
{
    __shared__ __align__(16) float sW[FF][FP];          // current (l,h) weight, padded
    __shared__ float s_asrc[FF];
    __shared__ float s_adst[FF];
    __shared__ __align__(16) float h_s[BB][NN][FP];     // head features / staging
    __shared__ float sdst_s[BB][NN];

    const int n   = threadIdx.x;            // node id 0..25
    const int bl  = threadIdx.y;            // local batch 0..7
    const int tid = bl * NN + n;            // 0..207
    const int b0  = blockIdx.x * BB;

    float* lin = &h_s[0][0][0];             // BB*NN*FP = 5824 floats >= 5408

    // ---- coalesced staging of x for this block ----
    {
        const float* src = x + (size_t)b0 * KDIM;
        #pragma unroll 4
        for (int i = tid; i < BB * KDIM; i += GAT_THREADS)
            lin[i] = src[i];
    }
    __syncthreads();

    float xrow[FF];
    #pragma unroll
    for (int f = 0; f < FF; f++)
        xrow[f] = lin[bl * KDIM + n * FF + f];
    // barrier inside head loop orders these reads vs. h_s overwrite

    float outacc[FP];

    for (int l = 0; l < L_LAYERS; l++) {
        #pragma unroll
        for (int f = 0; f < FP; f++) outacc[f] = 0.f;

        for (int h = 0; h < H_HEADS; h++) {
            __syncthreads();   // previous consumers of sW / h_s done

            // ---- stage W[l][h] (padded) and attention vectors ----
            const float* Wg = W + (size_t)(l * H_HEADS + h) * (FF * FF);
            for (int i = tid; i < FF * FF; i += GAT_THREADS) {
                int k = i / FF, o = i - k * FF;
                sW[k][o] = Wg[i];
            }
            if (tid < FF) {
                sW[tid][FF]   = 0.f;
                sW[tid][FF+1] = 0.f;
                s_asrc[tid] = a_src[(l * H_HEADS + h) * FF + tid];
                s_adst[tid] = a_dst[(l * H_HEADS + h) * FF + tid];
            }
            __syncthreads();

            // ---- step 1: hrow = xrow @ W  (register accumulators) ----
            float acc[FP];
            #pragma unroll
            for (int q = 0; q < FP; q++) acc[q] = 0.f;
            #pragma unroll
            for (int k = 0; k < FF; k++) {
                const float xk = xrow[k];
                const float4* wrow = reinterpret_cast<const float4*>(&sW[k][0]);
                #pragma unroll
                for (int q = 0; q < FP/4; q++) {
                    float4 w = wrow[q];
                    acc[4*q+0] += xk * w.x;
                    acc[4*q+1] += xk * w.y;
                    acc[4*q+2] += xk * w.z;
                    acc[4*q+3] += xk * w.w;
                }
            }
            // attention scores
            float ssrc = 0.f, sdst = 0.f;
            #pragma unroll
            for (int f = 0; f < FF; f++) {
                ssrc += acc[f] * s_asrc[f];
                sdst += acc[f] * s_adst[f];
            }
            // write h row (vectorized)
            {
                float4* hout = reinterpret_cast<float4*>(&h_s[bl][n][0]);
                #pragma unroll
                for (int q = 0; q < FP/4; q++) {
                    float4 v;
                    v.x = acc[4*q+0]; v.y = acc[4*q+1];
                    v.z = acc[4*q+2]; v.w = acc[4*q+3];
                    hout[q] = v;
                }
            }
            sdst_s[bl][n] = sdst;
            __syncthreads();

            // ---- step 2: leaky-relu + softmax over neighbors j ----
            float e[NN];
            float m = -1e30f;
            #pragma unroll
            for (int j = 0; j < NN; j++) {
                float v = ssrc + sdst_s[bl][j];
                v = fmaxf(v, 0.2f * v);        // leaky_relu(0.2), valid since slope<1
                e[j] = v;
                m = fmaxf(m, v);
            }
            float sum = 0.f;
            #pragma unroll
            for (int j = 0; j < NN; j++) {
                float p = __expf(e[j] - m);
                e[j] = p;
                sum += p;
            }
            const float inv = 1.0f / sum;

            // ---- step 3: aggregate alpha @ h into outacc ----
            #pragma unroll
            for (int j = 0; j < NN; j++) {
                const float aj = e[j] * inv;
                const float4* hrow = reinterpret_cast<const float4*>(&h_s[bl][j][0]);
                #pragma unroll
                for (int q = 0; q < FP/4; q++) {
                    float4 hv = hrow[q];
                    outacc[4*q+0] += aj * hv.x;
                    outacc[4*q+1] += aj * hv.y;
                    outacc[4*q+2] += aj * hv.z;
                    outacc[4*q+3] += aj * hv.w;
                }
            }
        } // heads

        // mean over heads + ELU
        #pragma unroll
        for (int f = 0; f < FF; f++) {
            float v = outacc[f] * 0.25f;
            xrow[f] = v > 0.f ? v : (__expf(v) - 1.f);
        }
    } // layers

    // ---- write flat output (coalesced via smem) ----
    __syncthreads();
    #pragma unroll
    for (int f = 0; f < FF; f++)
        lin[bl * KDIM + n * FF + f] = xrow[f];
    __syncthreads();
    {
        float* dst = g_flat + (size_t)b0 * KDIM;
        #pragma unroll 4
        for (int i = tid; i < BB * KDIM; i += GAT_THREADS)
            dst[i] = lin[i];
    }
    (void)batch;
}

// =====================================================================
// MLP kernel: out = lrelu(flat @ W1 + b1) @ W2 + b2
// Tiled SGEMM 64x256, K=676 (26 tiles of 26), fused epilogue.
// =====================================================================
__global__ __launch_bounds__(256, 2)
void mlp_kernel(const float* __restrict__ W1,
                const float* __restrict__ b1,
                const float* __restrict__ W2,
                const float* __restrict__ b2,
                float* __restrict__ out)
{
    __shared__ __align__(16) float As[MBK][MBM + 1];   // +1 pad: conflict-free store
    __shared__ __align__(16) float Bs[MBK][MBN];
    __shared__ float sb1[MBN];
    __shared__ float sW2[MBN][3];
    __shared__ float sb2[3];

    const int tid  = threadIdx.x;
    const int trow = tid >> 5;        // 0..7  -> row block (warp id)
    const int lane = tid & 31;        // 0..31 -> col block
    const int row0 = blockIdx.x * MBM;

    // stage epilogue constants
    if (tid < MBN) sb1[tid] = b1[tid];
    for (int i = tid; i < MBN * 3; i += 256) sW2[i / 3][i % 3] = W2[i];
    if (tid < 3) sb2[tid] = b2[tid];

    float acc[8][8];
    #pragma unroll
    for (int r = 0; r < 8; r++)
        #pragma unroll
        for (int c = 0; c < 8; c++) acc[r][c] = 0.f;

    for (int kt = 0; kt < KDIM / MBK; kt++) {
        __syncthreads();
        // A tile: flat[(row0+m)*676 + kt*26 + kk] -> As[kk][m]  (kk fastest: coalesced)
        for (int i = tid; i < MBM * MBK; i += 256) {
            int m = i / MBK, kk = i - m * MBK;
            As[kk][m] = g_flat[(size_t)(row0 + m) * KDIM + kt * MBK + kk];
        }
        // B tile: W1[(kt*26+kk)*256 + c] -> Bs[kk][c]  (coalesced, conflict-free)
        #pragma unroll
        for (int i = tid; i < MBK * MBN; i += 256) {
            int kk = i >> 8, c = i & 255;
            Bs[kk][c] = W1[(size_t)(kt * MBK + kk) * MBN + c];
        }
        __syncthreads();

        #pragma unroll
        for (int kk = 0; kk < MBK; kk++) {
            float a[8];
            #pragma unroll
            for (int r = 0; r < 8; r++) a[r] = As[kk][trow * 8 + r];   // broadcast
            float bb[8];
            const float4* brow = reinterpret_cast<const float4*>(&Bs[kk][lane * 8]);
            float4 b0v = brow[0], b1v = brow[1];
            bb[0]=b0v.x; bb[1]=b0v.y; bb[2]=b0v.z; bb[3]=b0v.w;
            bb[4]=b1v.x; bb[5]=b1v.y; bb[6]=b1v.z; bb[7]=b1v.w;
            #pragma unroll
            for (int r = 0; r < 8; r++)
                #pragma unroll
                for (int c = 0; c < 8; c++)
                    acc[r][c] += a[r] * bb[c];
        }
    }

    // ---- fused epilogue: bias + lrelu, then hdn @ W2, warp-reduce over cols ----
    float partial[8][3];
    #pragma unroll
    for (int r = 0; r < 8; r++)
        #pragma unroll
        for (int oc = 0; oc < 3; oc++) partial[r][oc] = 0.f;

    #pragma unroll
    for (int c = 0; c < 8; c++) {
        const int col = lane * 8 + c;
        const float bias = sb1[col];
        const float w0 = sW2[col][0], w1 = sW2[col][1], w2 = sW2[col][2];
        #pragma unroll
        for (int r = 0; r < 8; r++) {
            float v = acc[r][c] + bias;
            v = fmaxf(v, 0.2f * v);           // leaky_relu(0.2)
            partial[r][0] += v * w0;
            partial[r][1] += v * w1;
            partial[r][2] += v * w2;
        }
    }

    // each warp owns rows [trow*8, trow*8+8) exclusively -> shuffle reduce, lane 0 writes
    #pragma unroll
    for (int r = 0; r < 8; r++) {
        #pragma unroll
        for (int oc = 0; oc < 3; oc++) {
            float v = partial[r][oc];
            #pragma unroll
            for (int off = 16; off > 0; off >>= 1)
                v += __shfl_xor_sync(0xffffffffu, v, off);
            if (lane == 0)
                out[(size_t)(row0 + trow * 8 + r) * 3 + oc] = v + sb2[oc];
        }
    }
}

// =====================================================================
// launch
// =====================================================================
extern "C" void kernel_launch(void* const* d_in, const int* in_sizes, int n_in,
                              void* d_out, int out_size)
{
    // inputs (metadata order): dummy, x, W, a_src, a_dst, W1, b1, W2, b2
    const float* x     = (const float*)d_in[1];
    const float* W     = (const float*)d_in[2];
    const float* a_src = (const float*)d_in[3];
    const float* a_dst = (const float*)d_in[4];
    const float* W1    = (const float*)d_in[5];
    const float* b1    = (const float*)d_in[6];
    const float* W2    = (const float*)d_in[7];
    const float* b2    = (const float*)d_in[8];
    float* out = (float*)d_out;

    const int batch = in_sizes[1] / KDIM;   // 16384

    dim3 gthr(NN, BB);
    gat_kernel<<<batch / BB, gthr>>>(x, W, a_src, a_dst, batch);
    mlp_kernel<<<batch / MBM, 256>>>(W1, b1, W2, b2, out);
    (void)n_in; (void)out_size;
}

// round 2
// speedup vs baseline: 1.1277x; 1.1277x over previous
#include <cuda_runtime.h>
#include <cstddef>

// ---------------- problem constants ----------------
#define L_LAYERS 3
#define H_HEADS  4
#define NN       26       // nodes
#define FF       26       // features
#define FP       28       // padded feature dim (multiple of 4)
#define BB       16       // batch elements per GAT block
#define GAT_THREADS (BB*NN)   // 416 = 13 full warps
#define KDIM     (NN*FF)  // 676
#define HID      256

// MLP GEMM tiling
#define MBM 64
#define MBN 256
#define MBK 26            // 676 = 26 * 26 exact
#define MAP 72            // padded A row (multiple of 4, 16B-aligned rows)

// scratch for flattened GAT output: [B, 676]
__device__ float g_flat[16384 * KDIM];

// ---------------- packed fp32x2 helpers (sm_103a) ----------------
typedef unsigned long long u64t;

__device__ __forceinline__ u64t pack2(float lo, float hi) {
    u64t r;
    asm("mov.b64 %0, {%1,%2};" : "=l"(r) : "f"(lo), "f"(hi));
    return r;
}
__device__ __forceinline__ void unpack2(u64t v, float& lo, float& hi) {
    asm("mov.b64 {%0,%1}, %2;" : "=f"(lo), "=f"(hi) : "l"(v));
}
__device__ __forceinline__ u64t fma2(u64t a, u64t b, u64t c) {
    u64t d;
    asm("fma.rn.f32x2 %0, %1, %2, %3;" : "=l"(d) : "l"(a), "l"(b), "l"(c));
    return d;
}

// =====================================================================
// GAT kernel: 3 layers fused. Block = 16 batch elems x 26 nodes = 416 thr.
// All hot inner loops use packed fma.rn.f32x2 (2x fp32 throughput, exact).
// =====================================================================
__global__ __launch_bounds__(GAT_THREADS)
void gat_kernel(const float* __restrict__ x,
                const float* __restrict__ W,
                const float* __restrict__ a_src,
                const float* __restrict__ a_dst)
{
    __shared__ __align__(16) float sW[FF][FP];          // current (l,h) weight, padded
    __shared__ __align__(16) float s_asrc[FF];
    __shared__ __align__(16) float s_adst[FF];
    __shared__ __align__(16) float h_s[BB][NN][FP];     // head features / staging
    __shared__ float sdst_s[BB][NN];

    const int n   = threadIdx.x;            // node id 0..25
    const int bl  = threadIdx.y;            // local batch 0..15
    const int tid = bl * NN + n;            // 0..415
    const int b0  = blockIdx.x * BB;

    float* lin = &h_s[0][0][0];             // BB*NN*FP = 11648 floats >= 10816

    // zero the padding columns of sW once (never touched again)
    if (tid < FF) { sW[tid][FF] = 0.f; sW[tid][FF + 1] = 0.f; }

    // ---- coalesced vectorized staging of x for this block ----
    {
        const float4* src = reinterpret_cast<const float4*>(x + (size_t)b0 * KDIM);
        float4* dst = reinterpret_cast<float4*>(lin);
        for (int i = tid; i < BB * KDIM / 4; i += GAT_THREADS)
            dst[i] = src[i];
    }
    __syncthreads();

    float xrow[FF];
    #pragma unroll
    for (int f = 0; f < FF; f++)
        xrow[f] = lin[bl * KDIM + n * FF + f];
    // (head-loop barrier orders these reads vs. h_s overwrite)

    u64t outacc2[FP / 2];

    for (int l = 0; l < L_LAYERS; l++) {
        #pragma unroll
        for (int q = 0; q < FP / 2; q++) outacc2[q] = 0ULL;

        for (int h = 0; h < H_HEADS; h++) {
            __syncthreads();   // previous consumers of sW / h_s done

            // ---- stage W[l][h] and attention vectors ----
            const float* Wg = W + (size_t)(l * H_HEADS + h) * (FF * FF);
            for (int i = tid; i < FF * FF; i += GAT_THREADS) {
                int k = i / FF, o = i - k * FF;
                sW[k][o] = Wg[i];
            }
            if (tid < FF) {
                s_asrc[tid] = a_src[(l * H_HEADS + h) * FF + tid];
                s_adst[tid] = a_dst[(l * H_HEADS + h) * FF + tid];
            }
            __syncthreads();

            // ---- step 1: hrow = xrow @ W  (packed accumulators) ----
            u64t acc2[FP / 2];
            #pragma unroll
            for (int q = 0; q < FP / 2; q++) acc2[q] = 0ULL;

            #pragma unroll
            for (int k = 0; k < FF; k++) {
                const u64t xk2 = pack2(xrow[k], xrow[k]);
                const ulonglong2* wrow = reinterpret_cast<const ulonglong2*>(&sW[k][0]);
                #pragma unroll
                for (int q = 0; q < FP / 4; q++) {
                    ulonglong2 w = wrow[q];
                    acc2[2 * q + 0] = fma2(xk2, w.x, acc2[2 * q + 0]);
                    acc2[2 * q + 1] = fma2(xk2, w.y, acc2[2 * q + 1]);
                }
            }

            // ---- attention scores: packed dot over 13 pairs (f = 0..25) ----
            u64t ssrc2 = 0ULL, sdst2 = 0ULL;
            {
                const u64t* pa = reinterpret_cast<const u64t*>(s_asrc);
                const u64t* pd = reinterpret_cast<const u64t*>(s_adst);
                #pragma unroll
                for (int q = 0; q < FF / 2; q++) {
                    ssrc2 = fma2(acc2[q], pa[q], ssrc2);
                    sdst2 = fma2(acc2[q], pd[q], sdst2);
                }
            }
            float s0, s1, d0, d1;
            unpack2(ssrc2, s0, s1);
            unpack2(sdst2, d0, d1);
            const float ssrc = s0 + s1;
            const float sdst = d0 + d1;

            // write h row (128-bit stores of packed pairs)
            {
                ulonglong2* hout = reinterpret_cast<ulonglong2*>(&h_s[bl][n][0]);
                #pragma unroll
                for (int q = 0; q < FP / 4; q++) {
                    ulonglong2 v;
                    v.x = acc2[2 * q + 0];
                    v.y = acc2[2 * q + 1];
                    hout[q] = v;
                }
            }
            sdst_s[bl][n] = sdst;
            __syncthreads();

            // ---- step 2: leaky-relu + softmax over neighbors j ----
            float e[NN];
            float m = -1e30f;
            #pragma unroll
            for (int j = 0; j < NN; j++) {
                float v = ssrc + sdst_s[bl][j];
                v = fmaxf(v, 0.2f * v);        // leaky_relu(0.2)
                e[j] = v;
                m = fmaxf(m, v);
            }
            float sum = 0.f;
            #pragma unroll
            for (int j = 0; j < NN; j++) {
                float p = __expf(e[j] - m);
                e[j] = p;
                sum += p;
            }
            const float inv = 1.0f / sum;

            // ---- step 3: aggregate alpha @ h into outacc (packed) ----
            #pragma unroll
            for (int j = 0; j < NN; j++) {
                const float aj = e[j] * inv;
                const u64t aj2 = pack2(aj, aj);
                const ulonglong2* hrow = reinterpret_cast<const ulonglong2*>(&h_s[bl][j][0]);
                #pragma unroll
                for (int q = 0; q < FP / 4; q++) {
                    ulonglong2 hv = hrow[q];
                    outacc2[2 * q + 0] = fma2(aj2, hv.x, outacc2[2 * q + 0]);
                    outacc2[2 * q + 1] = fma2(aj2, hv.y, outacc2[2 * q + 1]);
                }
            }
        } // heads

        // mean over heads + ELU
        #pragma unroll
        for (int q = 0; q < FF / 2; q++) {
            float v0, v1;
            unpack2(outacc2[q], v0, v1);
            v0 *= 0.25f; v1 *= 0.25f;
            xrow[2 * q + 0] = v0 > 0.f ? v0 : (__expf(v0) - 1.f);
            xrow[2 * q + 1] = v1 > 0.f ? v1 : (__expf(v1) - 1.f);
        }
    } // layers

    // ---- write flat output (coalesced via smem) ----
    __syncthreads();
    #pragma unroll
    for (int f = 0; f < FF; f++)
        lin[bl * KDIM + n * FF + f] = xrow[f];
    __syncthreads();
    {
        float4* dst = reinterpret_cast<float4*>(g_flat + (size_t)b0 * KDIM);
        const float4* src = reinterpret_cast<const float4*>(lin);
        for (int i = tid; i < BB * KDIM / 4; i += GAT_THREADS)
            dst[i] = src[i];
    }
}

// =====================================================================
// MLP kernel: out = lrelu(flat @ W1 + b1) @ W2 + b2
// Tiled SGEMM 64x256, K=676 (26 tiles of 26), packed fma.rn.f32x2,
// fused epilogue (bias + lrelu + 256x3 second layer, warp-shuffle reduce).
// =====================================================================
__global__ __launch_bounds__(256, 2)
void mlp_kernel(const float* __restrict__ W1,
                const float* __restrict__ b1,
                const float* __restrict__ W2,
                const float* __restrict__ b2,
                float* __restrict__ out)
{
    __shared__ __align__(16) float As[MBK][MAP];       // padded, 16B-aligned rows
    __shared__ __align__(16) float Bs[MBK][MBN];
    __shared__ float sb1[MBN];
    __shared__ float sW2[MBN][3];
    __shared__ float sb2[3];

    const int tid  = threadIdx.x;
    const int trow = tid >> 5;        // 0..7  -> row block (warp id)
    const int lane = tid & 31;        // 0..31 -> col block
    const int row0 = blockIdx.x * MBM;

    // stage epilogue constants
    if (tid < MBN) sb1[tid] = b1[tid];
    for (int i = tid; i < MBN * 3; i += 256) sW2[i / 3][i % 3] = W2[i];
    if (tid < 3) sb2[tid] = b2[tid];

    // acc2[r][q]: packed pair of columns (lane*8 + 2q, lane*8 + 2q + 1)
    u64t acc2[8][4];
    #pragma unroll
    for (int r = 0; r < 8; r++)
        #pragma unroll
        for (int q = 0; q < 4; q++) acc2[r][q] = 0ULL;

    for (int kt = 0; kt < KDIM / MBK; kt++) {
        __syncthreads();
        // A tile: flat[(row0+m)*676 + kt*26 + kk] -> As[kk][m]
        for (int i = tid; i < MBM * MBK; i += 256) {
            int m = i / MBK, kk = i - m * MBK;
            As[kk][m] = g_flat[(size_t)(row0 + m) * KDIM + kt * MBK + kk];
        }
        // B tile: W1[(kt*26+kk)*256 + c] -> Bs[kk][c]
        #pragma unroll
        for (int i = tid; i < MBK * MBN; i += 256) {
            int kk = i >> 8, c = i & 255;
            Bs[kk][c] = W1[(size_t)(kt * MBK + kk) * MBN + c];
        }
        __syncthreads();

        #pragma unroll
        for (int kk = 0; kk < MBK; kk++) {
            // a[8] row values (broadcast across warp), 2x float4
            const float4* arow = reinterpret_cast<const float4*>(&As[kk][trow * 8]);
            float4 a0 = arow[0], a1 = arow[1];
            u64t ar2[8];
            ar2[0] = pack2(a0.x, a0.x); ar2[1] = pack2(a0.y, a0.y);
            ar2[2] = pack2(a0.z, a0.z); ar2[3] = pack2(a0.w, a0.w);
            ar2[4] = pack2(a1.x, a1.x); ar2[5] = pack2(a1.y, a1.y);
            ar2[6] = pack2(a1.z, a1.z); ar2[7] = pack2(a1.w, a1.w);

            // b pairs: 8 columns = 4 packed pairs, 2x LDS.128
            const ulonglong2* brow = reinterpret_cast<const ulonglong2*>(&Bs[kk][lane * 8]);
            ulonglong2 bv0 = brow[0], bv1 = brow[1];
            u64t bp[4];
            bp[0] = bv0.x; bp[1] = bv0.y; bp[2] = bv1.x; bp[3] = bv1.y;

            #pragma unroll
            for (int r = 0; r < 8; r++)
                #pragma unroll
                for (int q = 0; q < 4; q++)
                    acc2[r][q] = fma2(ar2[r], bp[q], acc2[r][q]);
        }
    }

    // ---- fused epilogue: bias + lrelu, then hdn @ W2, warp-reduce ----
    float partial[8][3];
    #pragma unroll
    for (int r = 0; r < 8; r++)
        #pragma unroll
        for (int oc = 0; oc < 3; oc++) partial[r][oc] = 0.f;

    #pragma unroll
    for (int q = 0; q < 4; q++) {
        const int c0 = lane * 8 + 2 * q;
        const float bias0 = sb1[c0], bias1 = sb1[c0 + 1];
        const float w00 = sW2[c0][0],   w01 = sW2[c0][1],   w02 = sW2[c0][2];
        const float w10 = sW2[c0+1][0], w11 = sW2[c0+1][1], w12 = sW2[c0+1][2];
        #pragma unroll
        for (int r = 0; r < 8; r++) {
            float v0, v1;
            unpack2(acc2[r][q], v0, v1);
            v0 += bias0; v1 += bias1;
            v0 = fmaxf(v0, 0.2f * v0);        // leaky_relu(0.2)
            v1 = fmaxf(v1, 0.2f * v1);
            partial[r][0] += v0 * w00 + v1 * w10;
            partial[r][1] += v0 * w01 + v1 * w11;
            partial[r][2] += v0 * w02 + v1 * w12;
        }
    }

    // each warp owns rows [trow*8, trow*8+8) exclusively
    #pragma unroll
    for (int r = 0; r < 8; r++) {
        #pragma unroll
        for (int oc = 0; oc < 3; oc++) {
            float v = partial[r][oc];
            #pragma unroll
            for (int off = 16; off > 0; off >>= 1)
                v += __shfl_xor_sync(0xffffffffu, v, off);
            if (lane == 0)
                out[(size_t)(row0 + trow * 8 + r) * 3 + oc] = v + sb2[oc];
        }
    }
}

// =====================================================================
// launch
// =====================================================================
extern "C" void kernel_launch(void* const* d_in, const int* in_sizes, int n_in,
                              void* d_out, int out_size)
{
    // inputs (metadata order): dummy, x, W, a_src, a_dst, W1, b1, W2, b2
    const float* x     = (const float*)d_in[1];
    const float* W     = (const float*)d_in[2];
    const float* a_src = (const float*)d_in[3];
    const float* a_dst = (const float*)d_in[4];
    const float* W1    = (const float*)d_in[5];
    const float* b1    = (const float*)d_in[6];
    const float* W2    = (const float*)d_in[7];
    const float* b2    = (const float*)d_in[8];
    float* out = (float*)d_out;

    const int batch = in_sizes[1] / KDIM;   // 16384

    dim3 gthr(NN, BB);
    gat_kernel<<<batch / BB, gthr>>>(x, W, a_src, a_dst);
    mlp_kernel<<<batch / MBM, 256>>>(W1, b1, W2, b2, out);
    (void)n_in; (void)out_size;
}

// round 4
// speedup vs baseline: 1.2861x; 1.1405x over previous
#include <cuda_runtime.h>
#include <cuda_bf16.h>
#include <cstdint>
#include <cstddef>

// ---------------- problem constants ----------------
#define L_LAYERS 3
#define H_HEADS  4
#define NN       26
#define FF       26
#define FP       28
#define BB       16
#define GAT_THREADS (BB*NN)   // 416
#define KDIM     (NN*FF)      // 676
#define KPAD     704          // 22 * 32
#define NCHUNK   22           // K chunks of 32
#define HID      256

// scratch: GAT output as bf16 hi/lo split, padded to KPAD cols
__device__ __nv_bfloat16 g_Ahi[16384 * KPAD];
__device__ __nv_bfloat16 g_Alo[16384 * KPAD];
// W1^T split: [256 n][KPAD k]
__device__ __nv_bfloat16 g_Bhi[256 * KPAD];
__device__ __nv_bfloat16 g_Blo[256 * KPAD];

// ---------------- packed fp32x2 helpers ----------------
typedef unsigned long long u64t;
__device__ __forceinline__ u64t pack2(float lo, float hi) {
    u64t r; asm("mov.b64 %0, {%1,%2};" : "=l"(r) : "f"(lo), "f"(hi)); return r;
}
__device__ __forceinline__ void unpack2(u64t v, float& lo, float& hi) {
    asm("mov.b64 {%0,%1}, %2;" : "=f"(lo), "=f"(hi) : "l"(v));
}
__device__ __forceinline__ u64t fma2(u64t a, u64t b, u64t c) {
    u64t d; asm("fma.rn.f32x2 %0, %1, %2, %3;" : "=l"(d) : "l"(a), "l"(b), "l"(c)); return d;
}

// ---------------- portable tensor-core helpers (sm_80+ PTX) ----------------
__device__ __forceinline__ uint32_t smem_u32(const void* p) {
    uint32_t a;
    asm("{ .reg .u64 t; cvta.to.shared.u64 t, %1; cvt.u32.u64 %0, t; }" : "=r"(a) : "l"(p));
    return a;
}
__device__ __forceinline__ void ldsm4(uint32_t* d, uint32_t addr) {
    asm volatile("ldmatrix.sync.aligned.m8n8.x4.shared.b16 {%0,%1,%2,%3}, [%4];"
                 : "=r"(d[0]), "=r"(d[1]), "=r"(d[2]), "=r"(d[3]) : "r"(addr));
}
__device__ __forceinline__ void mma16816(float* c, const uint32_t* a, uint32_t b0, uint32_t b1) {
    asm volatile(
        "mma.sync.aligned.m16n8k16.row.col.f32.bf16.bf16.f32 "
        "{%0,%1,%2,%3}, {%4,%5,%6,%7}, {%8,%9}, {%0,%1,%2,%3};"
        : "+f"(c[0]), "+f"(c[1]), "+f"(c[2]), "+f"(c[3])
        : "r"(a[0]), "r"(a[1]), "r"(a[2]), "r"(a[3]), "r"(b0), "r"(b1));
}
__device__ __forceinline__ void cp16(uint32_t dst, const void* src) {
    asm volatile("cp.async.ca.shared.global [%0], [%1], 16;" :: "r"(dst), "l"(src) : "memory");
}
#define CP_COMMIT() asm volatile("cp.async.commit_group;" ::: "memory")
#define CP_WAIT1()  asm volatile("cp.async.wait_group 1;" ::: "memory")
#define CP_WAIT0()  asm volatile("cp.async.wait_group 0;" ::: "memory")

// =====================================================================
// GAT kernel (fp32 FMA — near pipe ceiling): 3 layers fused.
// Output written as bf16 hi/lo split into g_Ahi/g_Alo [B, KPAD].
// =====================================================================
__global__ __launch_bounds__(GAT_THREADS)
void gat_kernel(const float* __restrict__ x,
                const float* __restrict__ W,
                const float* __restrict__ a_src,
                const float* __restrict__ a_dst)
{
    __shared__ __align__(16) float sW[FF][FP];
    __shared__ __align__(16) float s_asrc[FF];
    __shared__ __align__(16) float s_adst[FF];
    __shared__ __align__(16) float h_s[BB][NN][FP];
    __shared__ float sdst_s[BB][NN];

    const int n   = threadIdx.x;
    const int bl  = threadIdx.y;
    const int tid = bl * NN + n;
    const int b0  = blockIdx.x * BB;

    float* lin = &h_s[0][0][0];

    if (tid < FF) { sW[tid][FF] = 0.f; sW[tid][FF + 1] = 0.f; }

    {
        const float4* src = reinterpret_cast<const float4*>(x + (size_t)b0 * KDIM);
        float4* dst = reinterpret_cast<float4*>(lin);
        for (int i = tid; i < BB * KDIM / 4; i += GAT_THREADS)
            dst[i] = src[i];
    }
    __syncthreads();

    float xrow[FF];
    #pragma unroll
    for (int f = 0; f < FF; f++)
        xrow[f] = lin[bl * KDIM + n * FF + f];

    u64t outacc2[FP / 2];

    for (int l = 0; l < L_LAYERS; l++) {
        #pragma unroll
        for (int q = 0; q < FP / 2; q++) outacc2[q] = 0ULL;

        for (int h = 0; h < H_HEADS; h++) {
            __syncthreads();

            const float* Wg = W + (size_t)(l * H_HEADS + h) * (FF * FF);
            for (int i = tid; i < FF * FF; i += GAT_THREADS) {
                int k = i / FF, o = i - k * FF;
                sW[k][o] = Wg[i];
            }
            if (tid < FF) {
                s_asrc[tid] = a_src[(l * H_HEADS + h) * FF + tid];
                s_adst[tid] = a_dst[(l * H_HEADS + h) * FF + tid];
            }
            __syncthreads();

            u64t acc2[FP / 2];
            #pragma unroll
            for (int q = 0; q < FP / 2; q++) acc2[q] = 0ULL;

            #pragma unroll
            for (int k = 0; k < FF; k++) {
                const u64t xk2 = pack2(xrow[k], xrow[k]);
                const ulonglong2* wrow = reinterpret_cast<const ulonglong2*>(&sW[k][0]);
                #pragma unroll
                for (int q = 0; q < FP / 4; q++) {
                    ulonglong2 w = wrow[q];
                    acc2[2 * q + 0] = fma2(xk2, w.x, acc2[2 * q + 0]);
                    acc2[2 * q + 1] = fma2(xk2, w.y, acc2[2 * q + 1]);
                }
            }

            u64t ssrc2 = 0ULL, sdst2 = 0ULL;
            {
                const u64t* pa = reinterpret_cast<const u64t*>(s_asrc);
                const u64t* pd = reinterpret_cast<const u64t*>(s_adst);
                #pragma unroll
                for (int q = 0; q < FF / 2; q++) {
                    ssrc2 = fma2(acc2[q], pa[q], ssrc2);
                    sdst2 = fma2(acc2[q], pd[q], sdst2);
                }
            }
            float s0, s1, d0, d1;
            unpack2(ssrc2, s0, s1);
            unpack2(sdst2, d0, d1);
            const float ssrc = s0 + s1;
            const float sdst = d0 + d1;

            {
                ulonglong2* hout = reinterpret_cast<ulonglong2*>(&h_s[bl][n][0]);
                #pragma unroll
                for (int q = 0; q < FP / 4; q++) {
                    ulonglong2 v;
                    v.x = acc2[2 * q + 0];
                    v.y = acc2[2 * q + 1];
                    hout[q] = v;
                }
            }
            sdst_s[bl][n] = sdst;
            __syncthreads();

            float e[NN];
            float m = -1e30f;
            #pragma unroll
            for (int j = 0; j < NN; j++) {
                float v = ssrc + sdst_s[bl][j];
                v = fmaxf(v, 0.2f * v);
                e[j] = v;
                m = fmaxf(m, v);
            }
            float sum = 0.f;
            #pragma unroll
            for (int j = 0; j < NN; j++) {
                float p = __expf(e[j] - m);
                e[j] = p;
                sum += p;
            }
            const float inv = 1.0f / sum;

            #pragma unroll
            for (int j = 0; j < NN; j++) {
                const float aj = e[j] * inv;
                const u64t aj2 = pack2(aj, aj);
                const ulonglong2* hrow = reinterpret_cast<const ulonglong2*>(&h_s[bl][j][0]);
                #pragma unroll
                for (int q = 0; q < FP / 4; q++) {
                    ulonglong2 hv = hrow[q];
                    outacc2[2 * q + 0] = fma2(aj2, hv.x, outacc2[2 * q + 0]);
                    outacc2[2 * q + 1] = fma2(aj2, hv.y, outacc2[2 * q + 1]);
                }
            }
        } // heads

        #pragma unroll
        for (int q = 0; q < FF / 2; q++) {
            float v0, v1;
            unpack2(outacc2[q], v0, v1);
            v0 *= 0.25f; v1 *= 0.25f;
            xrow[2 * q + 0] = v0 > 0.f ? v0 : (__expf(v0) - 1.f);
            xrow[2 * q + 1] = v1 > 0.f ? v1 : (__expf(v1) - 1.f);
        }
    } // layers

    // ---- write bf16 hi/lo split, zero-padded to KPAD ----
    __syncthreads();
    #pragma unroll
    for (int f = 0; f < FF; f++)
        lin[bl * KDIM + n * FF + f] = xrow[f];
    __syncthreads();

    for (int i = tid; i < BB * (KPAD / 4); i += GAT_THREADS) {
        int row = i / (KPAD / 4);
        int cg  = i % (KPAD / 4);
        float4 v;
        if (cg < KDIM / 4)
            v = reinterpret_cast<const float4*>(lin + row * KDIM)[cg];
        else
            v = make_float4(0.f, 0.f, 0.f, 0.f);
        __nv_bfloat16 h0 = __float2bfloat16_rn(v.x), h1 = __float2bfloat16_rn(v.y);
        __nv_bfloat16 h2 = __float2bfloat16_rn(v.z), h3 = __float2bfloat16_rn(v.w);
        __nv_bfloat16 l0 = __float2bfloat16_rn(v.x - __bfloat162float(h0));
        __nv_bfloat16 l1 = __float2bfloat16_rn(v.y - __bfloat162float(h1));
        __nv_bfloat16 l2 = __float2bfloat16_rn(v.z - __bfloat162float(h2));
        __nv_bfloat16 l3 = __float2bfloat16_rn(v.w - __bfloat162float(h3));
        size_t o = (size_t)(b0 + row) * KPAD + cg * 4;
        __nv_bfloat162 a0; a0.x = h0; a0.y = h1;
        __nv_bfloat162 a1; a1.x = h2; a1.y = h3;
        __nv_bfloat162 c0; c0.x = l0; c0.y = l1;
        __nv_bfloat162 c1; c1.x = l2; c1.y = l3;
        *reinterpret_cast<__nv_bfloat162*>(&g_Ahi[o])     = a0;
        *reinterpret_cast<__nv_bfloat162*>(&g_Ahi[o + 2]) = a1;
        *reinterpret_cast<__nv_bfloat162*>(&g_Alo[o])     = c0;
        *reinterpret_cast<__nv_bfloat162*>(&g_Alo[o + 2]) = c1;
    }
}

// =====================================================================
// prep: W1^T bf16 hi/lo split, [256 n][KPAD k], zero-padded
// =====================================================================
__global__ void prep_w1(const float* __restrict__ W1)
{
    int i = blockIdx.x * 256 + threadIdx.x;
    if (i >= 256 * KPAD) return;
    int n = i / KPAD, k = i % KPAD;
    float v = (k < KDIM) ? W1[(size_t)k * HID + n] : 0.f;
    __nv_bfloat16 h = __float2bfloat16_rn(v);
    g_Bhi[i] = h;
    g_Blo[i] = __float2bfloat16_rn(v - __bfloat162float(h));
}

// =====================================================================
// MLP via mma.sync bf16 (3-term split): block 64 rows x 256 cols,
// 8 warps (warp_m 0..1 x warp_n 0..3), K-chunks of 32, cp.async 2-stage.
// Fused epilogue: bias + lrelu + (256x3) second layer.
// =====================================================================
// dynamic smem layout per stage (rows padded to 40 bf16 = 80B, conflict-free ldmatrix):
//   Ahi 64*80=5120B @0, Alo @5120, Bhi 256*80=20480B @10240, Blo @30720
#define STAGE_BYTES 51200
#define MLP_SMEM (2 * STAGE_BYTES)

__device__ __forceinline__ void copy_chunk(uint32_t smbase, int stage, int chunk,
                                           int row0, int tid)
{
    const uint32_t sb = smbase + stage * STAGE_BYTES;
    #pragma unroll
    for (int k = 0; k < 10; k++) {
        int u = tid + k * 256;
        if (u < 512) {
            int t = u >> 8, r = (u & 255) >> 2, seg = u & 3;
            const __nv_bfloat16* base = t ? g_Alo : g_Ahi;
            const __nv_bfloat16* src = base + (size_t)(row0 + r) * KPAD + chunk * 32 + seg * 8;
            cp16(sb + t * 5120 + r * 80 + seg * 16, src);
        } else {
            int v = u - 512;
            int t = v >> 10, r = (v & 1023) >> 2, seg = v & 3;
            const __nv_bfloat16* base = t ? g_Blo : g_Bhi;
            const __nv_bfloat16* src = base + (size_t)r * KPAD + chunk * 32 + seg * 8;
            cp16(sb + 10240 + t * 20480 + r * 80 + seg * 16, src);
        }
    }
}

__global__ __launch_bounds__(256, 2)
void mlp_mma(const float* __restrict__ b1,
             const float* __restrict__ W2,
             const float* __restrict__ b2,
             float* __restrict__ out)
{
    extern __shared__ __align__(16) char dsm[];
    __shared__ float sb1[HID];
    __shared__ float sW2[HID * 3];
    __shared__ float sb2s[3];
    __shared__ float red[64][13];

    const int tid = threadIdx.x, wid = tid >> 5, lane = tid & 31;
    const int warp_m = wid & 1;     // 0..1 -> 32-row half
    const int warp_n = wid >> 1;    // 0..3 -> 64-col slice
    const int row0 = blockIdx.x * 64;

    if (tid < HID) sb1[tid] = b1[tid];
    for (int i = tid; i < HID * 3; i += 256) sW2[i] = W2[i];
    if (tid < 3) sb2s[tid] = b2[tid];

    const uint32_t smbase = smem_u32(dsm);

    float acc[2][8][4];
    #pragma unroll
    for (int mt = 0; mt < 2; mt++)
        #pragma unroll
        for (int nt = 0; nt < 8; nt++)
            #pragma unroll
            for (int q = 0; q < 4; q++) acc[mt][nt][q] = 0.f;

    copy_chunk(smbase, 0, 0, row0, tid);
    CP_COMMIT();

    const int rpat = (lane & 7) + ((lane >> 3) & 1) * 8;

    for (int c = 0; c < NCHUNK; c++) {
        const int s = c & 1;
        if (c + 1 < NCHUNK) {
            copy_chunk(smbase, s ^ 1, c + 1, row0, tid);
            CP_COMMIT();
            CP_WAIT1();
        } else {
            CP_WAIT0();
        }
        __syncthreads();

        const uint32_t stB = smbase + s * STAGE_BYTES;
        #pragma unroll
        for (int ks = 0; ks < 2; ks++) {
            const int cpat = ks * 16 + (lane >> 4) * 8;

            uint32_t ah[2][4], al[2][4];
            #pragma unroll
            for (int mt = 0; mt < 2; mt++) {
                const uint32_t a_off =
                    (uint32_t)((warp_m * 32 + mt * 16 + rpat) * 80 + cpat * 2);
                ldsm4(ah[mt], stB + a_off);
                ldsm4(al[mt], stB + 5120 + a_off);
            }

            uint32_t bf[4][4];
            #pragma unroll
            for (int np = 0; np < 4; np++) {
                const uint32_t b_off =
                    (uint32_t)((warp_n * 64 + np * 16 + rpat) * 80 + cpat * 2);
                ldsm4(bf[np], stB + 10240 + b_off);
            }
            #pragma unroll
            for (int mt = 0; mt < 2; mt++)
                #pragma unroll
                for (int np = 0; np < 4; np++) {
                    mma16816(acc[mt][np * 2 + 0], ah[mt], bf[np][0], bf[np][2]);
                    mma16816(acc[mt][np * 2 + 1], ah[mt], bf[np][1], bf[np][3]);
                    mma16816(acc[mt][np * 2 + 0], al[mt], bf[np][0], bf[np][2]);
                    mma16816(acc[mt][np * 2 + 1], al[mt], bf[np][1], bf[np][3]);
                }
            #pragma unroll
            for (int np = 0; np < 4; np++) {
                const uint32_t b_off =
                    (uint32_t)((warp_n * 64 + np * 16 + rpat) * 80 + cpat * 2);
                ldsm4(bf[np], stB + 30720 + b_off);
            }
            #pragma unroll
            for (int mt = 0; mt < 2; mt++)
                #pragma unroll
                for (int np = 0; np < 4; np++) {
                    mma16816(acc[mt][np * 2 + 0], ah[mt], bf[np][0], bf[np][2]);
                    mma16816(acc[mt][np * 2 + 1], ah[mt], bf[np][1], bf[np][3]);
                }
        }
        __syncthreads();
    }

    // ---- fused epilogue ----
    #pragma unroll
    for (int mt = 0; mt < 2; mt++) {
        #pragma unroll
        for (int half = 0; half < 2; half++) {
            float s0 = 0.f, s1 = 0.f, s2 = 0.f;
            #pragma unroll
            for (int nt = 0; nt < 8; nt++) {
                const int col = warp_n * 64 + nt * 8 + (lane & 3) * 2;
                float v0 = acc[mt][nt][half * 2 + 0] + sb1[col];
                v0 = fmaxf(v0, 0.2f * v0);
                float v1 = acc[mt][nt][half * 2 + 1] + sb1[col + 1];
                v1 = fmaxf(v1, 0.2f * v1);
                s0 += v0 * sW2[col * 3 + 0] + v1 * sW2[(col + 1) * 3 + 0];
                s1 += v0 * sW2[col * 3 + 1] + v1 * sW2[(col + 1) * 3 + 1];
                s2 += v0 * sW2[col * 3 + 2] + v1 * sW2[(col + 1) * 3 + 2];
            }
            s0 += __shfl_xor_sync(0xffffffffu, s0, 1);
            s0 += __shfl_xor_sync(0xffffffffu, s0, 2);
            s1 += __shfl_xor_sync(0xffffffffu, s1, 1);
            s1 += __shfl_xor_sync(0xffffffffu, s1, 2);
            s2 += __shfl_xor_sync(0xffffffffu, s2, 1);
            s2 += __shfl_xor_sync(0xffffffffu, s2, 2);
            if ((lane & 3) == 0) {
                const int row = warp_m * 32 + mt * 16 + half * 8 + (lane >> 2);
                red[row][warp_n * 3 + 0] = s0;
                red[row][warp_n * 3 + 1] = s1;
                red[row][warp_n * 3 + 2] = s2;
            }
        }
    }
    __syncthreads();
    if (tid < 64) {
        const int row = tid;
        #pragma unroll
        for (int oc = 0; oc < 3; oc++) {
            float v = red[row][oc] + red[row][3 + oc] + red[row][6 + oc] +
                      red[row][9 + oc] + sb2s[oc];
            out[(size_t)(row0 + row) * 3 + oc] = v;
        }
    }
}

// =====================================================================
// launch
// =====================================================================
extern "C" void kernel_launch(void* const* d_in, const int* in_sizes, int n_in,
                              void* d_out, int out_size)
{
    const float* x     = (const float*)d_in[1];
    const float* W     = (const float*)d_in[2];
    const float* a_src = (const float*)d_in[3];
    const float* a_dst = (const float*)d_in[4];
    const float* W1    = (const float*)d_in[5];
    const float* b1    = (const float*)d_in[6];
    const float* W2    = (const float*)d_in[7];
    const float* b2    = (const float*)d_in[8];
    float* out = (float*)d_out;

    const int batch = in_sizes[1] / KDIM;   // 16384

    cudaFuncSetAttribute(mlp_mma, cudaFuncAttributeMaxDynamicSharedMemorySize, MLP_SMEM);

    prep_w1<<<(256 * KPAD + 255) / 256, 256>>>(W1);
    dim3 gthr(NN, BB);
    gat_kernel<<<batch / BB, gthr>>>(x, W, a_src, a_dst);
    mlp_mma<<<batch / 64, 256, MLP_SMEM>>>(b1, W2, b2, out);
    (void)n_in; (void)out_size;
}

// round 5
// speedup vs baseline: 1.9825x; 1.5415x over previous
#include <cuda_runtime.h>
#include <cuda_bf16.h>
#include <cstdint>
#include <cstddef>
#include <cstring>

// ---------------- problem constants ----------------
#define NN       26
#define KDIM     676
#define KPAD     704          // 22 * 32
#define NCHUNK   22
#define HID      256

// GAT output as bf16 hi/lo split [B, KPAD]
__device__ __nv_bfloat16 g_Ahi[16384 * KPAD];
__device__ __nv_bfloat16 g_Alo[16384 * KPAD];
// W1^T split: [256 n][KPAD k]
__device__ __nv_bfloat16 g_Bhi[256 * KPAD];
__device__ __nv_bfloat16 g_Blo[256 * KPAD];
// GAT weights, transposed + padded + split: [12 lh][32 o][40 f]
__device__ __nv_bfloat16 g_Wth[12 * 32 * 40];
__device__ __nv_bfloat16 g_Wtl[12 * 32 * 40];
// score vectors wsrc/wdst = W @ a_*: [12 lh][32 f]
__device__ float g_wsrc[12 * 32];
__device__ float g_wdst[12 * 32];

// ---------------- common helpers ----------------
__device__ __forceinline__ uint32_t smem_u32(const void* p) {
    uint32_t a;
    asm("{ .reg .u64 t; cvta.to.shared.u64 t, %1; cvt.u32.u64 %0, t; }" : "=r"(a) : "l"(p));
    return a;
}
__device__ __forceinline__ void ldsm4(uint32_t* d, uint32_t addr) {
    asm volatile("ldmatrix.sync.aligned.m8n8.x4.shared.b16 {%0,%1,%2,%3}, [%4];"
                 : "=r"(d[0]), "=r"(d[1]), "=r"(d[2]), "=r"(d[3]) : "r"(addr));
}
__device__ __forceinline__ void mma16816(float* c, const uint32_t* a, uint32_t b0, uint32_t b1) {
    asm volatile(
        "mma.sync.aligned.m16n8k16.row.col.f32.bf16.bf16.f32 "
        "{%0,%1,%2,%3}, {%4,%5,%6,%7}, {%8,%9}, {%0,%1,%2,%3};"
        : "+f"(c[0]), "+f"(c[1]), "+f"(c[2]), "+f"(c[3])
        : "r"(a[0]), "r"(a[1]), "r"(a[2]), "r"(a[3]), "r"(b0), "r"(b1));
}
__device__ __forceinline__ void cp16(uint32_t dst, const void* src) {
    asm volatile("cp.async.ca.shared.global [%0], [%1], 16;" :: "r"(dst), "l"(src) : "memory");
}
#define CP_COMMIT() asm volatile("cp.async.commit_group;" ::: "memory")
#define CP_WAIT1()  asm volatile("cp.async.wait_group 1;" ::: "memory")
#define CP_WAIT0()  asm volatile("cp.async.wait_group 0;" ::: "memory")

// split two floats into packed bf16x2 hi + lo correction
__device__ __forceinline__ void split2(float a, float b, uint32_t& hi, uint32_t& lo) {
    __nv_bfloat162 h = __floats2bfloat162_rn(a, b);
    float ra = a - __bfloat162float(h.x);
    float rb = b - __bfloat162float(h.y);
    __nv_bfloat162 l = __floats2bfloat162_rn(ra, rb);
    memcpy(&hi, &h, 4);
    memcpy(&lo, &l, 4);
}
__device__ __forceinline__ float actelu(float v) {
    return v > 0.f ? v : (__expf(v) - 1.f);
}

// =====================================================================
// prep kernels
// =====================================================================
__global__ void prep_w1(const float* __restrict__ W1)
{
    int i = blockIdx.x * 256 + threadIdx.x;
    if (i >= 256 * KPAD) return;
    int n = i / KPAD, k = i % KPAD;
    float v = (k < KDIM) ? W1[(size_t)k * HID + n] : 0.f;
    __nv_bfloat16 h = __float2bfloat16_rn(v);
    g_Bhi[i] = h;
    g_Blo[i] = __float2bfloat16_rn(v - __bfloat162float(h));
}

__global__ void prep_gat(const float* __restrict__ W,
                         const float* __restrict__ a_src,
                         const float* __restrict__ a_dst)
{
    int i = blockIdx.x * 256 + threadIdx.x;
    if (i < 12 * 32 * 40) {
        int lh = i / 1280, r = i % 1280, o = r / 40, f = r % 40;
        float v = (o < 26 && f < 26) ? W[((size_t)lh * 26 + f) * 26 + o] : 0.f;
        __nv_bfloat16 h = __float2bfloat16_rn(v);
        g_Wth[i] = h;
        g_Wtl[i] = __float2bfloat16_rn(v - __bfloat162float(h));
    } else {
        int j = i - 12 * 32 * 40;
        if (j < 12 * 32) {
            int lh = j / 32, f = j % 32;
            float s = 0.f, d = 0.f;
            if (f < 26) {
                for (int o = 0; o < 26; o++) {
                    float wv = W[((size_t)lh * 26 + f) * 26 + o];
                    s = fmaf(wv, a_src[lh * 26 + o], s);
                    d = fmaf(wv, a_dst[lh * 26 + o], d);
                }
            }
            g_wsrc[j] = s;
            g_wdst[j] = d;
        }
    }
}

// =====================================================================
// GAT on tensor cores: out = sum_h (alpha_h @ x) @ W_h, per-warp batch elem.
// 8 warps/block = 8 batch elems; alpha/x/W all bf16 hi/lo 3-term split.
// =====================================================================
#define XTH 0
#define XTL 20480
#define APH 40960
#define APL 61440
#define WTH 81920
#define WTL 92160
#define SDST 102400
#define SWS 106496
#define SWD 107008
#define GAT_SMEM 107520

__global__ __launch_bounds__(256, 2)
void gat_tc(const float* __restrict__ x)
{
    extern __shared__ char sm[];
    const uint32_t sb = smem_u32(sm);
    const int tid = threadIdx.x, w = tid >> 5, lane = tid & 31;
    const int b = blockIdx.x * 8 + w;

    // zero xT buffers once (pads stay zero forever)
    {
        uint4* p = (uint4*)(sm + XTH);
        for (int i = tid; i < (20480 * 2) / 16; i += 256)
            p[i] = make_uint4(0, 0, 0, 0);
    }
    __syncthreads();

    __nv_bfloat16* xth = (__nv_bfloat16*)(sm + XTH) + w * 1280;   // [32 f][40 j]
    __nv_bfloat16* xtl = (__nv_bfloat16*)(sm + XTL) + w * 1280;
    __nv_bfloat16* aph = (__nv_bfloat16*)(sm + APH) + w * 1280;   // [32 i][40 j]
    __nv_bfloat16* apl = (__nv_bfloat16*)(sm + APL) + w * 1280;
    float* sdst = (float*)(sm + SDST) + w * 128;                  // [4 h][32 j]
    float* sws  = (float*)(sm + SWS);                             // [4 h][32 f]
    float* swd  = (float*)(sm + SWD);

    // stage x (layer 0): transposed bf16 split
    for (int idx = lane; idx < KDIM; idx += 32) {
        int i = idx / 26, f = idx % 26;
        float v = x[(size_t)b * KDIM + idx];
        __nv_bfloat16 h = __float2bfloat16_rn(v);
        xth[f * 40 + i] = h;
        xtl[f * 40 + i] = __float2bfloat16_rn(v - __bfloat162float(h));
    }

    const int rpat = lane & 15;
    const int chalf = (lane >> 4) * 8;
    const uint32_t xthA = sb + XTH + w * 2560;
    const uint32_t xtlA = sb + XTL + w * 2560;
    const uint32_t aphA = sb + APH + w * 2560;
    const uint32_t aplA = sb + APL + w * 2560;

    for (int l = 0; l < 3; l++) {
        __syncthreads();   // xT writes done; W buffer free
        {
            const uint4* s0 = (const uint4*)(g_Wth + l * 5120);
            const uint4* s1 = (const uint4*)(g_Wtl + l * 5120);
            uint4* d0 = (uint4*)(sm + WTH);
            uint4* d1 = (uint4*)(sm + WTL);
            for (int i = tid; i < 640; i += 256) { d0[i] = s0[i]; d1[i] = s1[i]; }
            if (tid < 128) {
                ((float*)(sm + SWS))[tid] = g_wsrc[l * 128 + tid];
                ((float*)(sm + SWD))[tid] = g_wdst[l * 128 + tid];
            }
        }
        __syncthreads();

        // ---- scores: lane = node index ----
        float ssrc[4];
        {
            float xi[26];
            #pragma unroll
            for (int f = 0; f < 26; f++)
                xi[f] = __bfloat162float(xth[f * 40 + lane]) +
                        __bfloat162float(xtl[f * 40 + lane]);
            #pragma unroll
            for (int h = 0; h < 4; h++) {
                float s = 0.f, d = 0.f;
                #pragma unroll
                for (int f = 0; f < 26; f++) {
                    s = fmaf(xi[f], sws[h * 32 + f], s);
                    d = fmaf(xi[f], swd[h * 32 + f], d);
                }
                ssrc[h] = s;
                sdst[h * 32 + lane] = d;
            }
        }
        __syncwarp();

        float outf[2][4][4];
        #pragma unroll
        for (int mt = 0; mt < 2; mt++)
            #pragma unroll
            for (int nt = 0; nt < 4; nt++)
                #pragma unroll
                for (int q = 0; q < 4; q++) outf[mt][nt][q] = 0.f;

        for (int h = 0; h < 4; h++) {
            // ---- softmax row (lane = i; rows >=26 produce garbage, never used) ----
            float ev[26];
            float m = -1e30f;
            #pragma unroll
            for (int j = 0; j < 26; j++) {
                float v = ssrc[h] + sdst[h * 32 + j];
                v = fmaxf(v, 0.2f * v);
                ev[j] = v;
                m = fmaxf(m, v);
            }
            float su = 0.f;
            #pragma unroll
            for (int j = 0; j < 26; j++) {
                float p = __expf(ev[j] - m);
                ev[j] = p;
                su += p;
            }
            const float inv = 1.f / su;
            #pragma unroll
            for (int jj = 0; jj < 16; jj++) {
                float a0 = (2 * jj < 26) ? ev[(2 * jj < 26) ? 2 * jj : 0] * inv : 0.f;
                float a1 = (2 * jj + 1 < 26) ? ev[(2 * jj + 1 < 26) ? 2 * jj + 1 : 0] * inv : 0.f;
                uint32_t hi, lo;
                split2(a0, a1, hi, lo);
                *(uint32_t*)(aph + lane * 40 + 2 * jj) = hi;
                *(uint32_t*)(apl + lane * 40 + 2 * jj) = lo;
            }
            __syncwarp();

            // ---- step 1: Y = alpha @ x  (3-term split) ----
            float Yf[2][4][4];
            #pragma unroll
            for (int mt = 0; mt < 2; mt++)
                #pragma unroll
                for (int nt = 0; nt < 4; nt++)
                    #pragma unroll
                    for (int q = 0; q < 4; q++) Yf[mt][nt][q] = 0.f;

            #pragma unroll
            for (int ks = 0; ks < 2; ks++) {
                uint32_t Ah[2][4], Al[2][4], Xh[2][4], Xl[2][4];
                #pragma unroll
                for (int mt = 0; mt < 2; mt++) {
                    uint32_t off = (uint32_t)((mt * 16 + rpat) * 80 + (ks * 16 + chalf) * 2);
                    ldsm4(Ah[mt], aphA + off);
                    ldsm4(Al[mt], aplA + off);
                }
                #pragma unroll
                for (int nt = 0; nt < 2; nt++) {
                    uint32_t off = (uint32_t)((nt * 16 + rpat) * 80 + (ks * 16 + chalf) * 2);
                    ldsm4(Xh[nt], xthA + off);
                    ldsm4(Xl[nt], xtlA + off);
                }
                #pragma unroll
                for (int mt = 0; mt < 2; mt++)
                    #pragma unroll
                    for (int nt = 0; nt < 2; nt++) {
                        mma16816(Yf[mt][nt * 2],     Ah[mt], Xh[nt][0], Xh[nt][2]);
                        mma16816(Yf[mt][nt * 2 + 1], Ah[mt], Xh[nt][1], Xh[nt][3]);
                        mma16816(Yf[mt][nt * 2],     Ah[mt], Xl[nt][0], Xl[nt][2]);
                        mma16816(Yf[mt][nt * 2 + 1], Ah[mt], Xl[nt][1], Xl[nt][3]);
                        mma16816(Yf[mt][nt * 2],     Al[mt], Xh[nt][0], Xh[nt][2]);
                        mma16816(Yf[mt][nt * 2 + 1], Al[mt], Xh[nt][1], Xh[nt][3]);
                    }
            }

            // ---- in-register C -> A fragment conversion (split) ----
            uint32_t YAh[2][2][4], YAl[2][2][4];
            #pragma unroll
            for (int mt = 0; mt < 2; mt++)
                #pragma unroll
                for (int ks = 0; ks < 2; ks++) {
                    split2(Yf[mt][2 * ks][0],     Yf[mt][2 * ks][1],     YAh[mt][ks][0], YAl[mt][ks][0]);
                    split2(Yf[mt][2 * ks][2],     Yf[mt][2 * ks][3],     YAh[mt][ks][1], YAl[mt][ks][1]);
                    split2(Yf[mt][2 * ks + 1][0], Yf[mt][2 * ks + 1][1], YAh[mt][ks][2], YAl[mt][ks][2]);
                    split2(Yf[mt][2 * ks + 1][2], Yf[mt][2 * ks + 1][3], YAh[mt][ks][3], YAl[mt][ks][3]);
                }

            // ---- step 2: out += Y @ W_h ----
            #pragma unroll
            for (int ks = 0; ks < 2; ks++) {
                uint32_t Wh[2][4], Wl[2][4];
                #pragma unroll
                for (int ot = 0; ot < 2; ot++) {
                    uint32_t off = (uint32_t)((ot * 16 + rpat) * 80 + (ks * 16 + chalf) * 2);
                    ldsm4(Wh[ot], sb + WTH + h * 2560 + off);
                    ldsm4(Wl[ot], sb + WTL + h * 2560 + off);
                }
                #pragma unroll
                for (int mt = 0; mt < 2; mt++)
                    #pragma unroll
                    for (int ot = 0; ot < 2; ot++) {
                        mma16816(outf[mt][ot * 2],     YAh[mt][ks], Wh[ot][0], Wh[ot][2]);
                        mma16816(outf[mt][ot * 2 + 1], YAh[mt][ks], Wh[ot][1], Wh[ot][3]);
                        mma16816(outf[mt][ot * 2],     YAh[mt][ks], Wl[ot][0], Wl[ot][2]);
                        mma16816(outf[mt][ot * 2 + 1], YAh[mt][ks], Wl[ot][1], Wl[ot][3]);
                        mma16816(outf[mt][ot * 2],     YAl[mt][ks], Wh[ot][0], Wh[ot][2]);
                        mma16816(outf[mt][ot * 2 + 1], YAl[mt][ks], Wh[ot][1], Wh[ot][3]);
                    }
            }
        } // heads

        // ---- epilogue: mean + ELU, write next xT or final global split ----
        const int g = lane >> 2, tc2 = (lane & 3) * 2;
        if (l < 2) {
            #pragma unroll
            for (int mt = 0; mt < 2; mt++)
                #pragma unroll
                for (int nt = 0; nt < 4; nt++) {
                    int col = nt * 8 + tc2;
                    if (col < 26) {
                        #pragma unroll
                        for (int hf = 0; hf < 2; hf++) {
                            int row = mt * 16 + g + hf * 8;
                            if (row < 26) {
                                float v0 = actelu(outf[mt][nt][hf * 2]     * 0.25f);
                                float v1 = actelu(outf[mt][nt][hf * 2 + 1] * 0.25f);
                                __nv_bfloat16 h0 = __float2bfloat16_rn(v0);
                                __nv_bfloat16 h1 = __float2bfloat16_rn(v1);
                                xth[col * 40 + row] = h0;
                                xtl[col * 40 + row] = __float2bfloat16_rn(v0 - __bfloat162float(h0));
                                xth[(col + 1) * 40 + row] = h1;
                                xtl[(col + 1) * 40 + row] = __float2bfloat16_rn(v1 - __bfloat162float(h1));
                            }
                        }
                    }
                }
        } else {
            #pragma unroll
            for (int mt = 0; mt < 2; mt++)
                #pragma unroll
                for (int nt = 0; nt < 4; nt++) {
                    int col = nt * 8 + tc2;
                    if (col < 26) {
                        #pragma unroll
                        for (int hf = 0; hf < 2; hf++) {
                            int row = mt * 16 + g + hf * 8;
                            if (row < 26) {
                                float v0 = actelu(outf[mt][nt][hf * 2]     * 0.25f);
                                float v1 = actelu(outf[mt][nt][hf * 2 + 1] * 0.25f);
                                uint32_t hi, lo;
                                split2(v0, v1, hi, lo);
                                size_t o = (size_t)b * KPAD + row * 26 + col;
                                *(uint32_t*)&g_Ahi[o] = hi;
                                *(uint32_t*)&g_Alo[o] = lo;
                            }
                        }
                    }
                }
            if (lane < 28) {
                g_Ahi[(size_t)b * KPAD + KDIM + lane] = __float2bfloat16_rn(0.f);
                g_Alo[(size_t)b * KPAD + KDIM + lane] = __float2bfloat16_rn(0.f);
            }
        }
    } // layers
}

// =====================================================================
// MLP via mma.sync bf16 (3-term split) — unchanged from passing R4.
// =====================================================================
#define STAGE_BYTES 51200
#define MLP_SMEM (2 * STAGE_BYTES)

__device__ __forceinline__ void copy_chunk(uint32_t smbase, int stage, int chunk,
                                           int row0, int tid)
{
    const uint32_t sbs = smbase + stage * STAGE_BYTES;
    #pragma unroll
    for (int k = 0; k < 10; k++) {
        int u = tid + k * 256;
        if (u < 512) {
            int t = u >> 8, r = (u & 255) >> 2, seg = u & 3;
            const __nv_bfloat16* base = t ? g_Alo : g_Ahi;
            const __nv_bfloat16* src = base + (size_t)(row0 + r) * KPAD + chunk * 32 + seg * 8;
            cp16(sbs + t * 5120 + r * 80 + seg * 16, src);
        } else {
            int v = u - 512;
            int t = v >> 10, r = (v & 1023) >> 2, seg = v & 3;
            const __nv_bfloat16* base = t ? g_Blo : g_Bhi;
            const __nv_bfloat16* src = base + (size_t)r * KPAD + chunk * 32 + seg * 8;
            cp16(sbs + 10240 + t * 20480 + r * 80 + seg * 16, src);
        }
    }
}

__global__ __launch_bounds__(256, 2)
void mlp_mma(const float* __restrict__ b1,
             const float* __restrict__ W2,
             const float* __restrict__ b2,
             float* __restrict__ out)
{
    extern __shared__ __align__(16) char dsm[];
    __shared__ float sb1[HID];
    __shared__ float sW2[HID * 3];
    __shared__ float sb2s[3];
    __shared__ float red[64][13];

    const int tid = threadIdx.x, wid = tid >> 5, lane = tid & 31;
    const int warp_m = wid & 1;
    const int warp_n = wid >> 1;
    const int row0 = blockIdx.x * 64;

    if (tid < HID) sb1[tid] = b1[tid];
    for (int i = tid; i < HID * 3; i += 256) sW2[i] = W2[i];
    if (tid < 3) sb2s[tid] = b2[tid];

    const uint32_t smbase = smem_u32(dsm);

    float acc[2][8][4];
    #pragma unroll
    for (int mt = 0; mt < 2; mt++)
        #pragma unroll
        for (int nt = 0; nt < 8; nt++)
            #pragma unroll
            for (int q = 0; q < 4; q++) acc[mt][nt][q] = 0.f;

    copy_chunk(smbase, 0, 0, row0, tid);
    CP_COMMIT();

    const int rpat = lane & 15;

    for (int c = 0; c < NCHUNK; c++) {
        const int s = c & 1;
        if (c + 1 < NCHUNK) {
            copy_chunk(smbase, s ^ 1, c + 1, row0, tid);
            CP_COMMIT();
            CP_WAIT1();
        } else {
            CP_WAIT0();
        }
        __syncthreads();

        const uint32_t stB = smbase + s * STAGE_BYTES;
        #pragma unroll
        for (int ks = 0; ks < 2; ks++) {
            const int cpat = ks * 16 + (lane >> 4) * 8;

            uint32_t ah[2][4], al[2][4];
            #pragma unroll
            for (int mt = 0; mt < 2; mt++) {
                const uint32_t a_off =
                    (uint32_t)((warp_m * 32 + mt * 16 + rpat) * 80 + cpat * 2);
                ldsm4(ah[mt], stB + a_off);
                ldsm4(al[mt], stB + 5120 + a_off);
            }

            uint32_t bf[4][4];
            #pragma unroll
            for (int np = 0; np < 4; np++) {
                const uint32_t b_off =
                    (uint32_t)((warp_n * 64 + np * 16 + rpat) * 80 + cpat * 2);
                ldsm4(bf[np], stB + 10240 + b_off);
            }
            #pragma unroll
            for (int mt = 0; mt < 2; mt++)
                #pragma unroll
                for (int np = 0; np < 4; np++) {
                    mma16816(acc[mt][np * 2 + 0], ah[mt], bf[np][0], bf[np][2]);
                    mma16816(acc[mt][np * 2 + 1], ah[mt], bf[np][1], bf[np][3]);
                    mma16816(acc[mt][np * 2 + 0], al[mt], bf[np][0], bf[np][2]);
                    mma16816(acc[mt][np * 2 + 1], al[mt], bf[np][1], bf[np][3]);
                }
            #pragma unroll
            for (int np = 0; np < 4; np++) {
                const uint32_t b_off =
                    (uint32_t)((warp_n * 64 + np * 16 + rpat) * 80 + cpat * 2);
                ldsm4(bf[np], stB + 30720 + b_off);
            }
            #pragma unroll
            for (int mt = 0; mt < 2; mt++)
                #pragma unroll
                for (int np = 0; np < 4; np++) {
                    mma16816(acc[mt][np * 2 + 0], ah[mt], bf[np][0], bf[np][2]);
                    mma16816(acc[mt][np * 2 + 1], ah[mt], bf[np][1], bf[np][3]);
                }
        }
        __syncthreads();
    }

    #pragma unroll
    for (int mt = 0; mt < 2; mt++) {
        #pragma unroll
        for (int half = 0; half < 2; half++) {
            float s0 = 0.f, s1 = 0.f, s2 = 0.f;
            #pragma unroll
            for (int nt = 0; nt < 8; nt++) {
                const int col = warp_n * 64 + nt * 8 + (lane & 3) * 2;
                float v0 = acc[mt][nt][half * 2 + 0] + sb1[col];
                v0 = fmaxf(v0, 0.2f * v0);
                float v1 = acc[mt][nt][half * 2 + 1] + sb1[col + 1];
                v1 = fmaxf(v1, 0.2f * v1);
                s0 += v0 * sW2[col * 3 + 0] + v1 * sW2[(col + 1) * 3 + 0];
                s1 += v0 * sW2[col * 3 + 1] + v1 * sW2[(col + 1) * 3 + 1];
                s2 += v0 * sW2[col * 3 + 2] + v1 * sW2[(col + 1) * 3 + 2];
            }
            s0 += __shfl_xor_sync(0xffffffffu, s0, 1);
            s0 += __shfl_xor_sync(0xffffffffu, s0, 2);
            s1 += __shfl_xor_sync(0xffffffffu, s1, 1);
            s1 += __shfl_xor_sync(0xffffffffu, s1, 2);
            s2 += __shfl_xor_sync(0xffffffffu, s2, 1);
            s2 += __shfl_xor_sync(0xffffffffu, s2, 2);
            if ((lane & 3) == 0) {
                const int row = warp_m * 32 + mt * 16 + half * 8 + (lane >> 2);
                red[row][warp_n * 3 + 0] = s0;
                red[row][warp_n * 3 + 1] = s1;
                red[row][warp_n * 3 + 2] = s2;
            }
        }
    }
    __syncthreads();
    if (tid < 64) {
        const int row = tid;
        #pragma unroll
        for (int oc = 0; oc < 3; oc++) {
            float v = red[row][oc] + red[row][3 + oc] + red[row][6 + oc] +
                      red[row][9 + oc] + sb2s[oc];
            out[(size_t)(row0 + row) * 3 + oc] = v;
        }
    }
}

// =====================================================================
// launch
// =====================================================================
extern "C" void kernel_launch(void* const* d_in, const int* in_sizes, int n_in,
                              void* d_out, int out_size)
{
    const float* x     = (const float*)d_in[1];
    const float* W     = (const float*)d_in[2];
    const float* a_src = (const float*)d_in[3];
    const float* a_dst = (const float*)d_in[4];
    const float* W1    = (const float*)d_in[5];
    const float* b1    = (const float*)d_in[6];
    const float* W2    = (const float*)d_in[7];
    const float* b2    = (const float*)d_in[8];
    float* out = (float*)d_out;

    const int batch = in_sizes[1] / KDIM;   // 16384

    cudaFuncSetAttribute(gat_tc, cudaFuncAttributeMaxDynamicSharedMemorySize, GAT_SMEM);
    cudaFuncSetAttribute(mlp_mma, cudaFuncAttributeMaxDynamicSharedMemorySize, MLP_SMEM);

    prep_w1<<<(256 * KPAD + 255) / 256, 256>>>(W1);
    prep_gat<<<(12 * 32 * 40 + 12 * 32 + 255) / 256, 256>>>(W, a_src, a_dst);
    gat_tc<<<batch / 8, 256, GAT_SMEM>>>(x);
    mlp_mma<<<batch / 64, 256, MLP_SMEM>>>(b1, W2, b2, out);
    (void)n_in; (void)out_size;
}